// round 15
// baseline (speedup 1.0000x reference)
#include <cuda_runtime.h>
#include <cuda_bf16.h>
#include <math.h>
#include <stdint.h>

// Problem constants
constexpr int Bb = 2;
constexpr int Ss = 2048;
constexpr int Ee = 1024;
constexpr int Hh = 16;
constexpr int Dd = 64;
constexpr int KP = Ee / 2;   // packed u32 (bf16x2) per row

// Scratch (device globals — no allocation allowed)
// g_Q: pre-scaled by 0.125*log2(e), RNA-rounded tf32. g_K: RNA tf32, [B,H,S,D].
// g_V: RNA tf32, TRANSPOSED layout [B,H,D,S].
__device__ float g_Q[(size_t)Bb * Hh * Ss * Dd];
__device__ float g_K[(size_t)Bb * Hh * Ss * Dd];
__device__ float g_V[(size_t)Bb * Hh * Ss * Dd];
// Pre-packed bf16 hi/lo operands (u32 = 2 bf16, k-pairs minor)
__device__ uint32_t g_Wh[(size_t)4 * Ee * KP];     // weights, [z][n][kp]
__device__ uint32_t g_Wl[(size_t)4 * Ee * KP];
__device__ uint32_t g_Xh[(size_t)Bb * Ss * KP];    // x, [row][kp]
__device__ uint32_t g_Xl[(size_t)Bb * Ss * KP];
__device__ uint32_t g_AOh[(size_t)Bb * Ss * KP];   // attn out, [row][kp]
__device__ uint32_t g_AOl[(size_t)Bb * Ss * KP];

// ---------------------------------------------------------------------------
// Helpers
// ---------------------------------------------------------------------------
__device__ __forceinline__ uint32_t f2tf32(float f) {
    uint32_t u;
    asm("cvt.rna.tf32.f32 %0, %1;" : "=r"(u) : "f"(f));
    return u;
}

__device__ __forceinline__ float fast_exp2(float x) {
    float y;
    asm("ex2.approx.f32 %0, %1;" : "=f"(y) : "f"(x));
    return y;
}

__device__ __forceinline__ uint32_t pack_bf16x2(float e_even, float e_odd) {
    uint32_t r;
    asm("cvt.rn.bf16x2.f32 %0, %1, %2;" : "=r"(r) : "f"(e_odd), "f"(e_even));
    return r;
}

__device__ __forceinline__ void split2(float v0, float v1,
                                       uint32_t& hi, uint32_t& lo) {
    float h0 = __bfloat162float(__float2bfloat16(v0));
    float h1 = __bfloat162float(__float2bfloat16(v1));
    hi = pack_bf16x2(h0, h1);
    lo = pack_bf16x2(v0 - h0, v1 - h1);
}

__device__ __forceinline__ void mma_tf32(float c[4], uint32_t a0, uint32_t a1,
                                         uint32_t a2, uint32_t a3,
                                         uint32_t b0, uint32_t b1) {
    asm volatile(
        "mma.sync.aligned.m16n8k8.row.col.f32.tf32.tf32.f32 "
        "{%0,%1,%2,%3}, {%4,%5,%6,%7}, {%8,%9}, {%0,%1,%2,%3};\n"
        : "+f"(c[0]), "+f"(c[1]), "+f"(c[2]), "+f"(c[3])
        : "r"(a0), "r"(a1), "r"(a2), "r"(a3), "r"(b0), "r"(b1));
}

__device__ __forceinline__ void mma_bf16(float c[4], uint32_t a0, uint32_t a1,
                                         uint32_t a2, uint32_t a3,
                                         uint32_t b0, uint32_t b1) {
    asm volatile(
        "mma.sync.aligned.m16n8k16.row.col.f32.bf16.bf16.f32 "
        "{%0,%1,%2,%3}, {%4,%5,%6,%7}, {%8,%9}, {%0,%1,%2,%3};\n"
        : "+f"(c[0]), "+f"(c[1]), "+f"(c[2]), "+f"(c[3])
        : "r"(a0), "r"(a1), "r"(a2), "r"(a3), "r"(b0), "r"(b1));
}

__device__ __forceinline__ void ldsm_x4(uint32_t& r0, uint32_t& r1,
                                        uint32_t& r2, uint32_t& r3,
                                        uint32_t saddr) {
    asm volatile(
        "ldmatrix.sync.aligned.m8n8.x4.shared.b16 {%0,%1,%2,%3}, [%4];"
        : "=r"(r0), "=r"(r1), "=r"(r2), "=r"(r3) : "r"(saddr));
}

__device__ __forceinline__ void cp16(uint32_t dst_smem, const void* src) {
    asm volatile("cp.async.cg.shared.global [%0], [%1], 16;"
                 :: "r"(dst_smem), "l"(src));
}
__device__ __forceinline__ void cp_commit() {
    asm volatile("cp.async.commit_group;");
}
template <int N>
__device__ __forceinline__ void cp_wait() {
    asm volatile("cp.async.wait_group %0;" :: "n"(N));
}

// ---------------------------------------------------------------------------
// Kernel 0: weight + x pre-pack (z<4: W transpose+split; z==4: pack x).
// ---------------------------------------------------------------------------
__global__ __launch_bounds__(256) void prep_pack(
    const float* __restrict__ Wq, const float* __restrict__ Wk,
    const float* __restrict__ Wv, const float* __restrict__ Wo,
    const float* __restrict__ x)
{
    __shared__ float t[32][33];
    const int z = blockIdx.z;
    const int tid = threadIdx.x;

    if (z == 4) {
        int blk = blockIdx.y * 32 + blockIdx.x;
        #pragma unroll
        for (int it = 0; it < 4; it++) {
            int idx = (blk * 4 + it) * 256 + tid;
            float4 v = ((const float4*)x)[idx];
            uint32_t h0, l0, h1, l1;
            split2(v.x, v.y, h0, l0);
            split2(v.z, v.w, h1, l1);
            ((uint2*)g_Xh)[idx] = make_uint2(h0, h1);
            ((uint2*)g_Xl)[idx] = make_uint2(l0, l1);
        }
        return;
    }

    const int k0 = blockIdx.x * 32, n0 = blockIdx.y * 32;
    const float* W = (z == 0) ? Wq : (z == 1) ? Wk : (z == 2) ? Wv : Wo;

    #pragma unroll
    for (int it = 0; it < 4; it++) {
        int idx = tid + it * 256;
        int kk = idx >> 5, nn = idx & 31;
        float v;
        if (z < 3) {
            int n = n0 + nn, h = n >> 6, d = n & 63;
            v = W[((size_t)h * Ee + (k0 + kk)) * Dd + d];
        } else {
            v = W[(size_t)(k0 + kk) * Ee + (n0 + nn)];
        }
        t[kk][nn] = v;
    }
    __syncthreads();

    uint32_t* hi = g_Wh + (size_t)z * Ee * KP;
    uint32_t* lo = g_Wl + (size_t)z * Ee * KP;
    #pragma unroll
    for (int it = 0; it < 2; it++) {
        int idx = tid + it * 256;
        int nn = idx >> 4, kp = idx & 15;
        uint32_t h, l;
        split2(t[2 * kp][nn], t[2 * kp + 1][nn], h, l);
        size_t o = (size_t)(n0 + nn) * KP + (k0 >> 1) + kp;
        hi[o] = h; lo[o] = l;
    }
}

// ---------------------------------------------------------------------------
// 2-split bf16 GEMM (exact R11): 3-stage cp.async ring, ONE syncthreads per
// k-iter, compute THEN issue, 2 CTAs/SM. Compact stride-16 XOR smem.
// ---------------------------------------------------------------------------
constexpr int BM = 128, BN = 128, BK = 32;
constexpr int SEL_U32 = 128 * 16;                 // 2048 u32 per matrix sel
constexpr int STAGE_U32 = 4 * SEL_U32;            // 8192 u32 per stage
constexpr int NSTAGE = 3;
constexpr int GEMM_SMEM_BYTES = NSTAGE * STAGE_U32 * 4;   // 98304 B
constexpr int NKT = Ee / BK;                      // 32

__device__ __forceinline__ uint32_t sw_off(int row, int q) {
    return (uint32_t)(row * 16 + ((q ^ ((row >> 1) & 3)) << 2));
}

__device__ __forceinline__ void gemm_compute_bf16(
    uint32_t sBase, int st, int wm, int wn, int lane, float acc[4][4][4])
{
    const uint32_t aHi = sBase + (st * STAGE_U32) * 4;
    const uint32_t aLo = aHi + SEL_U32 * 4;
    const uint32_t bHi = aHi + 2 * SEL_U32 * 4;
    const uint32_t bLo = aHi + 3 * SEL_U32 * 4;
    const int mIdx = lane >> 3, lr = lane & 7;
    const int arow = (mIdx & 1) * 8 + lr, acol = (mIdx >> 1) * 4;
    const int brow = (mIdx >> 1) * 8 + lr, bcol = (mIdx & 1) * 4;

    #pragma unroll
    for (int s = 0; s < 2; s++) {
        const int cb = 8 * s;
        uint32_t bh_[4][2], bl_[4][2];
        #pragma unroll
        for (int p = 0; p < 2; p++) {
            int rowB = wn * 32 + p * 16 + brow;
            uint32_t off = sw_off(rowB, (cb + bcol) >> 2) * 4;
            ldsm_x4(bh_[2 * p][0], bh_[2 * p][1],
                    bh_[2 * p + 1][0], bh_[2 * p + 1][1], bHi + off);
            ldsm_x4(bl_[2 * p][0], bl_[2 * p][1],
                    bl_[2 * p + 1][0], bl_[2 * p + 1][1], bLo + off);
        }
        #pragma unroll
        for (int mt = 0; mt < 4; mt++) {
            int rowA = wm * 64 + mt * 16 + arow;
            uint32_t off = sw_off(rowA, (cb + acol) >> 2) * 4;
            uint32_t ah0, ah1, ah2, ah3, al0, al1, al2, al3;
            ldsm_x4(ah0, ah1, ah2, ah3, aHi + off);
            ldsm_x4(al0, al1, al2, al3, aLo + off);
            #pragma unroll
            for (int nt = 0; nt < 4; nt++)
                mma_bf16(acc[mt][nt], ah0, ah1, ah2, ah3, bh_[nt][0], bh_[nt][1]);
            #pragma unroll
            for (int nt = 0; nt < 4; nt++)
                mma_bf16(acc[mt][nt], ah0, ah1, ah2, ah3, bl_[nt][0], bl_[nt][1]);
            #pragma unroll
            for (int nt = 0; nt < 4; nt++)
                mma_bf16(acc[mt][nt], al0, al1, al2, al3, bh_[nt][0], bh_[nt][1]);
        }
    }
}

__device__ __forceinline__ void gemm_issue(
    uint32_t sBase, int st, int kt, int tid, int m0, int n0,
    const uint32_t* gAh, const uint32_t* gAl,
    const uint32_t* gBh, const uint32_t* gBl)
{
    const uint32_t stBase = sBase + (st * STAGE_U32) * 4;
    #pragma unroll
    for (int i = 0; i < 2; i++) {
        int f = tid + i * 256;
        int row = f >> 2, c4 = f & 3;
        uint32_t off = sw_off(row, c4) * 4;
        size_t oa = (size_t)(m0 + row) * KP + kt * 16 + c4 * 4;
        cp16(stBase + off, gAh + oa);
        cp16(stBase + SEL_U32 * 4 + off, gAl + oa);
        size_t ob = (size_t)(n0 + row) * KP + kt * 16 + c4 * 4;
        cp16(stBase + 2 * SEL_U32 * 4 + off, gBh + ob);
        cp16(stBase + 3 * SEL_U32 * 4 + off, gBl + ob);
    }
    cp_commit();
}

// Shared mainloop (exact R11: compute then issue).
__device__ __forceinline__ void gemm_mainloop(
    uint32_t sBase, int tid, int wm, int wn, int lane, int m0, int n0,
    const uint32_t* gAh, const uint32_t* gAl,
    const uint32_t* gBh, const uint32_t* gBl, float acc[4][4][4])
{
    gemm_issue(sBase, 0, 0, tid, m0, n0, gAh, gAl, gBh, gBl);
    gemm_issue(sBase, 1, 1, tid, m0, n0, gAh, gAl, gBh, gBl);

    int st = 0;
    for (int kt = 0; kt < NKT; kt++) {
        if (kt + 1 < NKT) cp_wait<1>(); else cp_wait<0>();
        __syncthreads();
        gemm_compute_bf16(sBase, st, wm, wn, lane, acc);
        if (kt + 2 < NKT) {
            int st2 = st + 2; if (st2 >= NSTAGE) st2 -= NSTAGE;
            gemm_issue(sBase, st2, kt + 2, tid, m0, n0, gAh, gAl, gBh, gBl);
        }
        if (++st == NSTAGE) st = 0;
    }
}

// ---------------------------------------------------------------------------
// Kernel 1: fused QKV projection. Q pre-scaled+rounded; K rounded; V rounded
// and written TRANSPOSED [B,H,D,S].
// ---------------------------------------------------------------------------
__global__ __launch_bounds__(256, 2) void proj_qkv_tc(
    const float* __restrict__ bq, const float* __restrict__ bk,
    const float* __restrict__ bv)
{
    extern __shared__ uint32_t sm[];
    const int tid = threadIdx.x;
    const int lane = tid & 31, wid = tid >> 5;
    const int wm = wid >> 2, wn = wid & 3;
    const int g = lane >> 2, tig = lane & 3;

    const int z = blockIdx.z;
    const float* bias = (z == 0) ? bq : (z == 1) ? bk : bv;
    const float oscale = (z == 0) ? 0.125f * 1.44269504089f : 1.0f;
    const uint32_t* gBh = g_Wh + (size_t)z * Ee * KP;
    const uint32_t* gBl = g_Wl + (size_t)z * Ee * KP;

    const int m0 = blockIdx.x * BM;
    const int n0 = blockIdx.y * BN;

    uint32_t sBase = (uint32_t)__cvta_generic_to_shared(sm);

    float acc[4][4][4];
    #pragma unroll
    for (int mt = 0; mt < 4; mt++)
        #pragma unroll
        for (int nt = 0; nt < 4; nt++)
            #pragma unroll
            for (int v = 0; v < 4; v++) acc[mt][nt][v] = 0.f;

    gemm_mainloop(sBase, tid, wm, wn, lane, m0, n0, g_Xh, g_Xl, gBh, gBl, acc);

    #pragma unroll
    for (int mt = 0; mt < 4; mt++) {
        #pragma unroll
        for (int nt = 0; nt < 4; nt++) {
            int col = n0 + wn * 32 + nt * 8 + tig * 2;
            int h = col >> 6, d = col & 63;
            float b0 = bias[h * Dd + d], b1 = bias[h * Dd + d + 1];
            int m = m0 + wm * 64 + mt * 16 + g;
            #pragma unroll
            for (int rr = 0; rr < 2; rr++) {
                int row = m + rr * 8;
                int b = row >> 11, s = row & 2047;
                float v0 = __uint_as_float(
                    f2tf32((acc[mt][nt][rr * 2 + 0] + b0) * oscale));
                float v1 = __uint_as_float(
                    f2tf32((acc[mt][nt][rr * 2 + 1] + b1) * oscale));
                if (z == 2) {
                    size_t base = ((size_t)(b * Hh + h) * Dd + d) * Ss + s;
                    g_V[base]      = v0;
                    g_V[base + Ss] = v1;
                } else {
                    float* out = (z == 0) ? g_Q : g_K;
                    float* o = out + (((size_t)(b * Hh + h)) * Ss + s) * Dd + d;
                    o[0] = v0;
                    o[1] = v1;
                }
            }
        }
    }
}

// ---------------------------------------------------------------------------
// Kernel 3: output projection (reads packed attn output).
// ---------------------------------------------------------------------------
__global__ __launch_bounds__(256, 2) void out_proj_tc(float* __restrict__ out)
{
    extern __shared__ uint32_t sm[];
    const int tid = threadIdx.x;
    const int lane = tid & 31, wid = tid >> 5;
    const int wm = wid >> 2, wn = wid & 3;
    const int g = lane >> 2, tig = lane & 3;

    const uint32_t* gBh = g_Wh + (size_t)3 * Ee * KP;
    const uint32_t* gBl = g_Wl + (size_t)3 * Ee * KP;

    const int m0 = blockIdx.x * BM;
    const int n0 = blockIdx.y * BN;

    uint32_t sBase = (uint32_t)__cvta_generic_to_shared(sm);

    float acc[4][4][4];
    #pragma unroll
    for (int mt = 0; mt < 4; mt++)
        #pragma unroll
        for (int nt = 0; nt < 4; nt++)
            #pragma unroll
            for (int v = 0; v < 4; v++) acc[mt][nt][v] = 0.f;

    gemm_mainloop(sBase, tid, wm, wn, lane, m0, n0, g_AOh, g_AOl, gBh, gBl, acc);

    #pragma unroll
    for (int mt = 0; mt < 4; mt++) {
        #pragma unroll
        for (int nt = 0; nt < 4; nt++) {
            int col = n0 + wn * 32 + nt * 8 + tig * 2;
            int m = m0 + wm * 64 + mt * 16 + g;
            #pragma unroll
            for (int rr = 0; rr < 2; rr++) {
                int row = m + rr * 8;
                out[(size_t)row * Ee + col]     = acc[mt][nt][rr * 2 + 0];
                out[(size_t)row * Ee + col + 1] = acc[mt][nt][rr * 2 + 1];
            }
        }
    }
}

// ---------------------------------------------------------------------------
// Kernel 2: causal flash attention, SOFTWARE PIPELINED: QK(t+1) issued into a
// second fragment set before softmax(t)/PV(t), so tensor pipe overlaps MUFU.
// q/KV tiles 128, 256 threads, double-buffered cp.async, base-2 softmax.
// ---------------------------------------------------------------------------
constexpr int QSTR = 132;
constexpr int KSTR = 68;
constexpr int VTSTR = 132;
constexpr int ATTN_SMEM_BYTES =
    (128 * QSTR + 2 * 128 * KSTR + 2 * 64 * VTSTR) * 4;  // 204800 B

__global__ __launch_bounds__(256, 1) void attn_tc()
{
    extern __shared__ uint32_t smu[];
    uint32_t* Ps = smu;
    uint32_t* Ks = smu + 128 * QSTR;
    uint32_t* Vs = Ks + 2 * 128 * KSTR;

    const int qt = 15 - (int)blockIdx.x;
    const int bh = blockIdx.y;
    const int q0 = qt * 128;
    const int ntiles = qt + 1;

    const float* Qg = g_Q + (size_t)bh * Ss * Dd;
    const float* Kg = g_K + (size_t)bh * Ss * Dd;
    const float* Vtg = g_V + (size_t)bh * Dd * Ss;

    const int tid = threadIdx.x;
    const int lane = tid & 31;
    const int w = tid >> 5;
    const int g = lane >> 2;
    const int tig = lane & 3;
    const int w16 = w * 16;
    const int mIdx = lane >> 3, lr = lane & 7;
    const int parow = (mIdx & 1) * 8 + lr, pacol = (mIdx >> 1) * 4;
    const int kbrow = (mIdx >> 1) * 8 + lr, kbcol = (mIdx & 1) * 4;

    const uint32_t sP = (uint32_t)__cvta_generic_to_shared(Ps);
    const uint32_t sK = (uint32_t)__cvta_generic_to_shared(Ks);
    const uint32_t sV = (uint32_t)__cvta_generic_to_shared(Vs);

    auto issue_kv = [&](int t, int b) {
        const int k0 = t * 128;
        #pragma unroll
        for (int i = 0; i < 8; i++) {
            int f = tid + i * 256;
            int r = f >> 4, c4 = f & 15;
            cp16(sK + (b * 128 * KSTR + r * KSTR + c4 * 4) * 4,
                 Kg + (size_t)(k0 + r) * Dd + c4 * 4);
        }
        #pragma unroll
        for (int i = 0; i < 8; i++) {
            int f = tid + i * 256;
            int r = f >> 5, c4 = f & 31;
            cp16(sV + (b * 64 * VTSTR + r * VTSTR + c4 * 4) * 4,
                 Vtg + (size_t)r * Ss + k0 + c4 * 4);
        }
        cp_commit();
    };

    issue_kv(0, 0);
    if (ntiles > 1) issue_kv(1, 1);

    // Stage Q tile (pre-scaled, tf32-rounded in global)
    #pragma unroll
    for (int i = 0; i < 8; i++) {
        int f = tid + i * 256;
        int r = f >> 4, c4 = f & 15;
        float4 v = *(const float4*)(Qg + (size_t)(q0 + r) * Dd + c4 * 4);
        *(uint4*)(Ps + r * QSTR + c4 * 4) =
            make_uint4(__float_as_uint(v.x), __float_as_uint(v.y),
                       __float_as_uint(v.z), __float_as_uint(v.w));
    }

    // Wait for KV tile 0 (leave tile 1's group pending if it exists)
    if (ntiles > 1) cp_wait<1>(); else cp_wait<0>();
    __syncthreads();

    uint32_t qf[8][4];
    #pragma unroll
    for (int kk = 0; kk < 8; kk++) {
        uint32_t addr = sP + (uint32_t)((w16 + parow) * QSTR + kk * 8 + pacol) * 4;
        ldsm_x4(qf[kk][0], qf[kk][1], qf[kk][2], qf[kk][3], addr);
    }

    // QK for a tile in smem buffer b -> sacc
    auto qk = [&](float (&sacc)[16][4], int b) {
        #pragma unroll
        for (int nf = 0; nf < 16; nf++)
            #pragma unroll
            for (int v = 0; v < 4; v++) sacc[nf][v] = 0.f;
        const uint32_t sKb = sK + (uint32_t)(b * 128 * KSTR) * 4;
        #pragma unroll
        for (int kk = 0; kk < 8; kk++) {
            #pragma unroll
            for (int p = 0; p < 8; p++) {
                uint32_t addr = sKb +
                    (uint32_t)((p * 16 + kbrow) * KSTR + kk * 8 + kbcol) * 4;
                uint32_t b0a, b1a, b0b, b1b;
                ldsm_x4(b0a, b1a, b0b, b1b, addr);
                mma_tf32(sacc[2 * p], qf[kk][0], qf[kk][1], qf[kk][2],
                         qf[kk][3], b0a, b1a);
                mma_tf32(sacc[2 * p + 1], qf[kk][0], qf[kk][1], qf[kk][2],
                         qf[kk][3], b0b, b1b);
            }
        }
    };

    float saccA[16][4], saccB[16][4];
    qk(saccA, 0);

    float oacc[8][4];
    #pragma unroll
    for (int nf = 0; nf < 8; nf++)
        #pragma unroll
        for (int v = 0; v < 4; v++) oacc[nf][v] = 0.f;
    float mrow[2] = {-1e30f, -1e30f};
    float lrow[2] = {0.f, 0.f};

    for (int t = 0; t < ntiles; t++) {
        const int buf = t & 1;
        const bool has_next = (t + 1 < ntiles);

        // Pipeline: QK(t+1) first — its MMAs overlap softmax(t)'s MUFU/ALU.
        if (has_next) {
            cp_wait<0>();
            __syncthreads();
            qk(saccB, buf ^ 1);
        }

        const int kv0 = t * 128;
        const bool domask = (t == ntiles - 1);

        // Online softmax (base-2) on saccA
        #pragma unroll
        for (int r = 0; r < 2; r++) {
            const int rowg = q0 + w16 + g + 8 * r;
            float mt = -1e30f;
            #pragma unroll
            for (int nf = 0; nf < 16; nf++) {
                float s0 = saccA[nf][2 * r];
                float s1 = saccA[nf][2 * r + 1];
                if (domask) {
                    int col = kv0 + nf * 8 + 2 * tig;
                    if (col > rowg)     s0 = -1e30f;
                    if (col + 1 > rowg) s1 = -1e30f;
                }
                saccA[nf][2 * r] = s0; saccA[nf][2 * r + 1] = s1;
                mt = fmaxf(mt, fmaxf(s0, s1));
            }
            mt = fmaxf(mt, __shfl_xor_sync(0xffffffffu, mt, 1, 4));
            mt = fmaxf(mt, __shfl_xor_sync(0xffffffffu, mt, 2, 4));
            float mnew = fmaxf(mrow[r], mt);
            float corr = fast_exp2(mrow[r] - mnew);
            float rs = 0.f;
            #pragma unroll
            for (int nf = 0; nf < 16; nf++) {
                float p0 = fast_exp2(saccA[nf][2 * r] - mnew);
                float p1 = fast_exp2(saccA[nf][2 * r + 1] - mnew);
                rs += p0 + p1;
                *(uint2*)(Ps + (w16 + g + 8 * r) * QSTR + nf * 8 + 2 * tig) =
                    make_uint2(f2tf32(p0), f2tf32(p1));
            }
            rs += __shfl_xor_sync(0xffffffffu, rs, 1, 4);
            rs += __shfl_xor_sync(0xffffffffu, rs, 2, 4);
            lrow[r] = lrow[r] * corr + rs;
            mrow[r] = mnew;
            #pragma unroll
            for (int nf = 0; nf < 8; nf++) {
                oacc[nf][2 * r]     *= corr;
                oacc[nf][2 * r + 1] *= corr;
            }
        }
        __syncwarp();

        // O += P @ V  (V^T B-frags via ldmatrix)
        const uint32_t sVb = sV + (uint32_t)(buf * 64 * VTSTR) * 4;
        #pragma unroll
        for (int kk = 0; kk < 16; kk++) {
            uint32_t a0, a1, a2, a3;
            ldsm_x4(a0, a1, a2, a3,
                    sP + (uint32_t)((w16 + parow) * QSTR + kk * 8 + pacol) * 4);
            uint32_t bv_[8][2];
            #pragma unroll
            for (int p = 0; p < 4; p++) {
                uint32_t addr = sVb +
                    (uint32_t)((p * 16 + kbrow) * VTSTR + kk * 8 + kbcol) * 4;
                ldsm_x4(bv_[2 * p][0], bv_[2 * p][1],
                        bv_[2 * p + 1][0], bv_[2 * p + 1][1], addr);
            }
            #pragma unroll
            for (int nf = 0; nf < 8; nf++)
                mma_tf32(oacc[nf], a0, a1, a2, a3, bv_[nf][0], bv_[nf][1]);
        }

        __syncthreads();
        if (t + 2 < ntiles) issue_kv(t + 2, buf);

        if (has_next) {
            #pragma unroll
            for (int nf = 0; nf < 16; nf++)
                #pragma unroll
                for (int v = 0; v < 4; v++) saccA[nf][v] = saccB[nf][v];
        }
    }

    // Epilogue: normalize + write PACKED bf16 hi/lo [B*S][kp]
    const int b = bh >> 4, h = bh & 15;
    #pragma unroll
    for (int r = 0; r < 2; r++) {
        float inv = 1.0f / lrow[r];
        int s = q0 + w16 + g + 8 * r;
        size_t rowbase = (size_t)(b * Ss + s) * KP;
        #pragma unroll
        for (int nf = 0; nf < 8; nf++) {
            int d = nf * 8 + 2 * tig;
            float o0 = oacc[nf][2 * r] * inv;
            float o1 = oacc[nf][2 * r + 1] * inv;
            uint32_t hi, lo;
            split2(o0, o1, hi, lo);
            size_t off = rowbase + ((h * Dd + d) >> 1);
            g_AOh[off] = hi;
            g_AOl[off] = lo;
        }
    }
}

// ---------------------------------------------------------------------------
// Launch
// ---------------------------------------------------------------------------
extern "C" void kernel_launch(void* const* d_in, const int* in_sizes, int n_in,
                              void* d_out, int out_size)
{
    const float* x  = (const float*)d_in[0];
    const float* Wq = (const float*)d_in[1];
    const float* bq = (const float*)d_in[2];
    const float* Wk = (const float*)d_in[3];
    const float* bk = (const float*)d_in[4];
    const float* Wv = (const float*)d_in[5];
    const float* bv = (const float*)d_in[6];
    const float* Wo = (const float*)d_in[7];
    float* out = (float*)d_out;

    static bool attr_set = false;
    if (!attr_set) {
        cudaFuncSetAttribute(proj_qkv_tc,
            cudaFuncAttributeMaxDynamicSharedMemorySize, GEMM_SMEM_BYTES);
        cudaFuncSetAttribute(out_proj_tc,
            cudaFuncAttributeMaxDynamicSharedMemorySize, GEMM_SMEM_BYTES);
        cudaFuncSetAttribute(attn_tc,
            cudaFuncAttributeMaxDynamicSharedMemorySize, ATTN_SMEM_BYTES);
        attr_set = true;
    }

    // Pre-pack weights (z 0..3) and x (z == 4)
    prep_pack<<<dim3(32, 32, 5), 256>>>(Wq, Wk, Wv, Wo, x);

    // QKV projections
    proj_qkv_tc<<<dim3(32, 8, 3), 256, GEMM_SMEM_BYTES>>>(bq, bk, bv);

    // Flash attention: 16 q-tiles x 32 (b,h)
    attn_tc<<<dim3(16, Bb * Hh), 256, ATTN_SMEM_BYTES>>>();

    // Output projection
    out_proj_tc<<<dim3(32, 8), 256, GEMM_SMEM_BYTES>>>(out);
}

// round 16
// speedup vs baseline: 1.2500x; 1.2500x over previous
#include <cuda_runtime.h>
#include <cuda_bf16.h>
#include <cuda_fp16.h>
#include <math.h>
#include <stdint.h>

// Problem constants
constexpr int Bb = 2;
constexpr int Ss = 2048;
constexpr int Ee = 1024;
constexpr int Hh = 16;
constexpr int Dd = 64;
constexpr int KP = Ee / 2;   // packed u32 (bf16x2) per row

// Scratch (device globals — no allocation allowed)
// Q: pre-scaled by 0.125*log2(e), fp16x2-packed [B,H,S,D/2]. K: fp16x2 packed.
// V: fp16 TRANSPOSED [B,H,D,S].
__device__ uint32_t g_Qp[(size_t)Bb * Hh * Ss * (Dd / 2)];
__device__ uint32_t g_Kp[(size_t)Bb * Hh * Ss * (Dd / 2)];
__device__ uint32_t g_Vp[(size_t)Bb * Hh * Dd * (Ss / 2)];
// Pre-packed bf16 hi/lo operands (u32 = 2 bf16, k-pairs minor)
__device__ uint32_t g_Wh[(size_t)4 * Ee * KP];     // weights, [z][n][kp]
__device__ uint32_t g_Wl[(size_t)4 * Ee * KP];
__device__ uint32_t g_Xh[(size_t)Bb * Ss * KP];    // x, [row][kp]
__device__ uint32_t g_Xl[(size_t)Bb * Ss * KP];
__device__ uint32_t g_AOh[(size_t)Bb * Ss * KP];   // attn out, [row][kp]
__device__ uint32_t g_AOl[(size_t)Bb * Ss * KP];

// ---------------------------------------------------------------------------
// Helpers
// ---------------------------------------------------------------------------
__device__ __forceinline__ float fast_exp2(float x) {
    float y;
    asm("ex2.approx.f32 %0, %1;" : "=f"(y) : "f"(x));
    return y;
}

__device__ __forceinline__ uint32_t pack_bf16x2(float e_even, float e_odd) {
    uint32_t r;
    asm("cvt.rn.bf16x2.f32 %0, %1, %2;" : "=r"(r) : "f"(e_odd), "f"(e_even));
    return r;
}

__device__ __forceinline__ void split2(float v0, float v1,
                                       uint32_t& hi, uint32_t& lo) {
    float h0 = __bfloat162float(__float2bfloat16(v0));
    float h1 = __bfloat162float(__float2bfloat16(v1));
    hi = pack_bf16x2(h0, h1);
    lo = pack_bf16x2(v0 - h0, v1 - h1);
}

__device__ __forceinline__ uint32_t packh2(float a, float b) {
    __half2 h = __floats2half2_rn(a, b);   // low = a, high = b
    return *(uint32_t*)&h;
}

__device__ __forceinline__ void mma_f16(float c[4], uint32_t a0, uint32_t a1,
                                        uint32_t a2, uint32_t a3,
                                        uint32_t b0, uint32_t b1) {
    asm volatile(
        "mma.sync.aligned.m16n8k16.row.col.f32.f16.f16.f32 "
        "{%0,%1,%2,%3}, {%4,%5,%6,%7}, {%8,%9}, {%0,%1,%2,%3};\n"
        : "+f"(c[0]), "+f"(c[1]), "+f"(c[2]), "+f"(c[3])
        : "r"(a0), "r"(a1), "r"(a2), "r"(a3), "r"(b0), "r"(b1));
}

__device__ __forceinline__ void mma_bf16(float c[4], uint32_t a0, uint32_t a1,
                                         uint32_t a2, uint32_t a3,
                                         uint32_t b0, uint32_t b1) {
    asm volatile(
        "mma.sync.aligned.m16n8k16.row.col.f32.bf16.bf16.f32 "
        "{%0,%1,%2,%3}, {%4,%5,%6,%7}, {%8,%9}, {%0,%1,%2,%3};\n"
        : "+f"(c[0]), "+f"(c[1]), "+f"(c[2]), "+f"(c[3])
        : "r"(a0), "r"(a1), "r"(a2), "r"(a3), "r"(b0), "r"(b1));
}

__device__ __forceinline__ void ldsm_x4(uint32_t& r0, uint32_t& r1,
                                        uint32_t& r2, uint32_t& r3,
                                        uint32_t saddr) {
    asm volatile(
        "ldmatrix.sync.aligned.m8n8.x4.shared.b16 {%0,%1,%2,%3}, [%4];"
        : "=r"(r0), "=r"(r1), "=r"(r2), "=r"(r3) : "r"(saddr));
}

__device__ __forceinline__ void cp16(uint32_t dst_smem, const void* src) {
    asm volatile("cp.async.cg.shared.global [%0], [%1], 16;"
                 :: "r"(dst_smem), "l"(src));
}
__device__ __forceinline__ void cp_commit() {
    asm volatile("cp.async.commit_group;");
}
template <int N>
__device__ __forceinline__ void cp_wait() {
    asm volatile("cp.async.wait_group %0;" :: "n"(N));
}

// ---------------------------------------------------------------------------
// Kernel 0: weight + x pre-pack (z<4: W transpose+split; z==4: pack x).
// ---------------------------------------------------------------------------
__global__ __launch_bounds__(256) void prep_pack(
    const float* __restrict__ Wq, const float* __restrict__ Wk,
    const float* __restrict__ Wv, const float* __restrict__ Wo,
    const float* __restrict__ x)
{
    __shared__ float t[32][33];
    const int z = blockIdx.z;
    const int tid = threadIdx.x;

    if (z == 4) {
        int blk = blockIdx.y * 32 + blockIdx.x;
        #pragma unroll
        for (int it = 0; it < 4; it++) {
            int idx = (blk * 4 + it) * 256 + tid;
            float4 v = ((const float4*)x)[idx];
            uint32_t h0, l0, h1, l1;
            split2(v.x, v.y, h0, l0);
            split2(v.z, v.w, h1, l1);
            ((uint2*)g_Xh)[idx] = make_uint2(h0, h1);
            ((uint2*)g_Xl)[idx] = make_uint2(l0, l1);
        }
        return;
    }

    const int k0 = blockIdx.x * 32, n0 = blockIdx.y * 32;
    const float* W = (z == 0) ? Wq : (z == 1) ? Wk : (z == 2) ? Wv : Wo;

    #pragma unroll
    for (int it = 0; it < 4; it++) {
        int idx = tid + it * 256;
        int kk = idx >> 5, nn = idx & 31;
        float v;
        if (z < 3) {
            int n = n0 + nn, h = n >> 6, d = n & 63;
            v = W[((size_t)h * Ee + (k0 + kk)) * Dd + d];
        } else {
            v = W[(size_t)(k0 + kk) * Ee + (n0 + nn)];
        }
        t[kk][nn] = v;
    }
    __syncthreads();

    uint32_t* hi = g_Wh + (size_t)z * Ee * KP;
    uint32_t* lo = g_Wl + (size_t)z * Ee * KP;
    #pragma unroll
    for (int it = 0; it < 2; it++) {
        int idx = tid + it * 256;
        int nn = idx >> 4, kp = idx & 15;
        uint32_t h, l;
        split2(t[2 * kp][nn], t[2 * kp + 1][nn], h, l);
        size_t o = (size_t)(n0 + nn) * KP + (k0 >> 1) + kp;
        hi[o] = h; lo[o] = l;
    }
}

// ---------------------------------------------------------------------------
// 2-split bf16 GEMM (exact R11): 3-stage cp.async ring, ONE syncthreads per
// k-iter, compute THEN issue, 2 CTAs/SM. Compact stride-16 XOR smem.
// ---------------------------------------------------------------------------
constexpr int BM = 128, BN = 128, BK = 32;
constexpr int SEL_U32 = 128 * 16;
constexpr int STAGE_U32 = 4 * SEL_U32;
constexpr int NSTAGE = 3;
constexpr int GEMM_SMEM_BYTES = NSTAGE * STAGE_U32 * 4;   // 98304 B
constexpr int NKT = Ee / BK;                      // 32

__device__ __forceinline__ uint32_t sw_off(int row, int q) {
    return (uint32_t)(row * 16 + ((q ^ ((row >> 1) & 3)) << 2));
}

__device__ __forceinline__ void gemm_compute_bf16(
    uint32_t sBase, int st, int wm, int wn, int lane, float acc[4][4][4])
{
    const uint32_t aHi = sBase + (st * STAGE_U32) * 4;
    const uint32_t aLo = aHi + SEL_U32 * 4;
    const uint32_t bHi = aHi + 2 * SEL_U32 * 4;
    const uint32_t bLo = aHi + 3 * SEL_U32 * 4;
    const int mIdx = lane >> 3, lr = lane & 7;
    const int arow = (mIdx & 1) * 8 + lr, acol = (mIdx >> 1) * 4;
    const int brow = (mIdx >> 1) * 8 + lr, bcol = (mIdx & 1) * 4;

    #pragma unroll
    for (int s = 0; s < 2; s++) {
        const int cb = 8 * s;
        uint32_t bh_[4][2], bl_[4][2];
        #pragma unroll
        for (int p = 0; p < 2; p++) {
            int rowB = wn * 32 + p * 16 + brow;
            uint32_t off = sw_off(rowB, (cb + bcol) >> 2) * 4;
            ldsm_x4(bh_[2 * p][0], bh_[2 * p][1],
                    bh_[2 * p + 1][0], bh_[2 * p + 1][1], bHi + off);
            ldsm_x4(bl_[2 * p][0], bl_[2 * p][1],
                    bl_[2 * p + 1][0], bl_[2 * p + 1][1], bLo + off);
        }
        #pragma unroll
        for (int mt = 0; mt < 4; mt++) {
            int rowA = wm * 64 + mt * 16 + arow;
            uint32_t off = sw_off(rowA, (cb + acol) >> 2) * 4;
            uint32_t ah0, ah1, ah2, ah3, al0, al1, al2, al3;
            ldsm_x4(ah0, ah1, ah2, ah3, aHi + off);
            ldsm_x4(al0, al1, al2, al3, aLo + off);
            #pragma unroll
            for (int nt = 0; nt < 4; nt++)
                mma_bf16(acc[mt][nt], ah0, ah1, ah2, ah3, bh_[nt][0], bh_[nt][1]);
            #pragma unroll
            for (int nt = 0; nt < 4; nt++)
                mma_bf16(acc[mt][nt], ah0, ah1, ah2, ah3, bl_[nt][0], bl_[nt][1]);
            #pragma unroll
            for (int nt = 0; nt < 4; nt++)
                mma_bf16(acc[mt][nt], al0, al1, al2, al3, bh_[nt][0], bh_[nt][1]);
        }
    }
}

__device__ __forceinline__ void gemm_issue(
    uint32_t sBase, int st, int kt, int tid, int m0, int n0,
    const uint32_t* gAh, const uint32_t* gAl,
    const uint32_t* gBh, const uint32_t* gBl)
{
    const uint32_t stBase = sBase + (st * STAGE_U32) * 4;
    #pragma unroll
    for (int i = 0; i < 2; i++) {
        int f = tid + i * 256;
        int row = f >> 2, c4 = f & 3;
        uint32_t off = sw_off(row, c4) * 4;
        size_t oa = (size_t)(m0 + row) * KP + kt * 16 + c4 * 4;
        cp16(stBase + off, gAh + oa);
        cp16(stBase + SEL_U32 * 4 + off, gAl + oa);
        size_t ob = (size_t)(n0 + row) * KP + kt * 16 + c4 * 4;
        cp16(stBase + 2 * SEL_U32 * 4 + off, gBh + ob);
        cp16(stBase + 3 * SEL_U32 * 4 + off, gBl + ob);
    }
    cp_commit();
}

__device__ __forceinline__ void gemm_mainloop(
    uint32_t sBase, int tid, int wm, int wn, int lane, int m0, int n0,
    const uint32_t* gAh, const uint32_t* gAl,
    const uint32_t* gBh, const uint32_t* gBl, float acc[4][4][4])
{
    gemm_issue(sBase, 0, 0, tid, m0, n0, gAh, gAl, gBh, gBl);
    gemm_issue(sBase, 1, 1, tid, m0, n0, gAh, gAl, gBh, gBl);

    int st = 0;
    for (int kt = 0; kt < NKT; kt++) {
        if (kt + 1 < NKT) cp_wait<1>(); else cp_wait<0>();
        __syncthreads();
        gemm_compute_bf16(sBase, st, wm, wn, lane, acc);
        if (kt + 2 < NKT) {
            int st2 = st + 2; if (st2 >= NSTAGE) st2 -= NSTAGE;
            gemm_issue(sBase, st2, kt + 2, tid, m0, n0, gAh, gAl, gBh, gBl);
        }
        if (++st == NSTAGE) st = 0;
    }
}

// ---------------------------------------------------------------------------
// Kernel 1: fused QKV projection. Outputs fp16: Q (pre-scaled) / K packed
// half2 [B,H,S,D/2]; V fp16 transposed [B,H,D,S].
// ---------------------------------------------------------------------------
__global__ __launch_bounds__(256, 2) void proj_qkv_tc(
    const float* __restrict__ bq, const float* __restrict__ bk,
    const float* __restrict__ bv)
{
    extern __shared__ uint32_t sm[];
    const int tid = threadIdx.x;
    const int lane = tid & 31, wid = tid >> 5;
    const int wm = wid >> 2, wn = wid & 3;
    const int g = lane >> 2, tig = lane & 3;

    const int z = blockIdx.z;
    const float* bias = (z == 0) ? bq : (z == 1) ? bk : bv;
    const float oscale = (z == 0) ? 0.125f * 1.44269504089f : 1.0f;
    const uint32_t* gBh = g_Wh + (size_t)z * Ee * KP;
    const uint32_t* gBl = g_Wl + (size_t)z * Ee * KP;

    const int m0 = blockIdx.x * BM;
    const int n0 = blockIdx.y * BN;

    uint32_t sBase = (uint32_t)__cvta_generic_to_shared(sm);

    float acc[4][4][4];
    #pragma unroll
    for (int mt = 0; mt < 4; mt++)
        #pragma unroll
        for (int nt = 0; nt < 4; nt++)
            #pragma unroll
            for (int v = 0; v < 4; v++) acc[mt][nt][v] = 0.f;

    gemm_mainloop(sBase, tid, wm, wn, lane, m0, n0, g_Xh, g_Xl, gBh, gBl, acc);

    #pragma unroll
    for (int mt = 0; mt < 4; mt++) {
        #pragma unroll
        for (int nt = 0; nt < 4; nt++) {
            int col = n0 + wn * 32 + nt * 8 + tig * 2;
            int h = col >> 6, d = col & 63;
            float b0 = bias[h * Dd + d], b1 = bias[h * Dd + d + 1];
            int m = m0 + wm * 64 + mt * 16 + g;
            #pragma unroll
            for (int rr = 0; rr < 2; rr++) {
                int row = m + rr * 8;
                int b = row >> 11, s = row & 2047;
                float v0 = (acc[mt][nt][rr * 2 + 0] + b0) * oscale;
                float v1 = (acc[mt][nt][rr * 2 + 1] + b1) * oscale;
                if (z == 2) {
                    __half* vt = (__half*)g_Vp;
                    size_t base = ((size_t)(b * Hh + h) * Dd + d) * Ss + s;
                    vt[base]      = __float2half_rn(v0);
                    vt[base + Ss] = __float2half_rn(v1);
                } else {
                    uint32_t* out = (z == 0) ? g_Qp : g_Kp;
                    out[((size_t)(b * Hh + h) * Ss + s) * (Dd / 2) + (d >> 1)] =
                        packh2(v0, v1);
                }
            }
        }
    }
}

// ---------------------------------------------------------------------------
// Kernel 3: output projection (reads packed attn output).
// ---------------------------------------------------------------------------
__global__ __launch_bounds__(256, 2) void out_proj_tc(float* __restrict__ out)
{
    extern __shared__ uint32_t sm[];
    const int tid = threadIdx.x;
    const int lane = tid & 31, wid = tid >> 5;
    const int wm = wid >> 2, wn = wid & 3;
    const int g = lane >> 2, tig = lane & 3;

    const uint32_t* gBh = g_Wh + (size_t)3 * Ee * KP;
    const uint32_t* gBl = g_Wl + (size_t)3 * Ee * KP;

    const int m0 = blockIdx.x * BM;
    const int n0 = blockIdx.y * BN;

    uint32_t sBase = (uint32_t)__cvta_generic_to_shared(sm);

    float acc[4][4][4];
    #pragma unroll
    for (int mt = 0; mt < 4; mt++)
        #pragma unroll
        for (int nt = 0; nt < 4; nt++)
            #pragma unroll
            for (int v = 0; v < 4; v++) acc[mt][nt][v] = 0.f;

    gemm_mainloop(sBase, tid, wm, wn, lane, m0, n0, g_AOh, g_AOl, gBh, gBl, acc);

    #pragma unroll
    for (int mt = 0; mt < 4; mt++) {
        #pragma unroll
        for (int nt = 0; nt < 4; nt++) {
            int col = n0 + wn * 32 + nt * 8 + tig * 2;
            int m = m0 + wm * 64 + mt * 16 + g;
            #pragma unroll
            for (int rr = 0; rr < 2; rr++) {
                int row = m + rr * 8;
                out[(size_t)row * Ee + col]     = acc[mt][nt][rr * 2 + 0];
                out[(size_t)row * Ee + col + 1] = acc[mt][nt][rr * 2 + 1];
            }
        }
    }
}

// ---------------------------------------------------------------------------
// Kernel 2: causal flash attention, fp16 m16n8k16 MMA (half the MMAs of the
// tf32 version; fp16 mantissa == tf32 mantissa so numerics are equivalent).
// R11 structure: q/KV tiles 128, 256 threads, double-buffered cp.async,
// base-2 softmax, ldmatrix everywhere.
// Smem (u32): P/Q [128][68], K [2][128][36], V^T [2][64][68].
// ---------------------------------------------------------------------------
constexpr int QSTR = 68;    // P/Q region stride (u32): 64 data + 4 pad
constexpr int KSTR = 36;    // K: 32 data + 4 pad
constexpr int VTSTR = 68;   // V^T: 64 data + 4 pad
constexpr int ATTN_SMEM_BYTES =
    (128 * QSTR + 2 * 128 * KSTR + 2 * 64 * VTSTR) * 4;  // 106496 B

__global__ __launch_bounds__(256, 1) void attn_tc()
{
    extern __shared__ uint32_t smu[];
    uint32_t* Ps = smu;                        // [128][68]  Q then P
    uint32_t* Ks = smu + 128 * QSTR;           // [2][128][36]
    uint32_t* Vs = Ks + 2 * 128 * KSTR;        // [2][64][68]

    const int qt = 15 - (int)blockIdx.x;       // heavy first
    const int bh = blockIdx.y;
    const int q0 = qt * 128;
    const int ntiles = qt + 1;

    const uint32_t* Qg = g_Qp + (size_t)bh * Ss * (Dd / 2);
    const uint32_t* Kg = g_Kp + (size_t)bh * Ss * (Dd / 2);
    const uint32_t* Vg = g_Vp + (size_t)bh * Dd * (Ss / 2);

    const int tid = threadIdx.x;
    const int lane = tid & 31;
    const int w = tid >> 5;
    const int g = lane >> 2;
    const int tig = lane & 3;
    const int w16 = w * 16;
    const int mIdx = lane >> 3, lr = lane & 7;
    const int parow = (mIdx & 1) * 8 + lr, pacol = (mIdx >> 1) * 4;
    const int kbrow = (mIdx >> 1) * 8 + lr, kbcol = (mIdx & 1) * 4;

    const uint32_t sP = (uint32_t)__cvta_generic_to_shared(Ps);
    const uint32_t sK = (uint32_t)__cvta_generic_to_shared(Ks);
    const uint32_t sV = (uint32_t)__cvta_generic_to_shared(Vs);

    auto issue_kv = [&](int t, int b) {
        const int k0 = t * 128;
        // K tile: 128 rows x 32 u32 = 1024 chunks of 16B -> 4 per thread
        #pragma unroll
        for (int i = 0; i < 4; i++) {
            int f = tid + i * 256;
            int r = f >> 3, c4 = f & 7;
            cp16(sK + (b * 128 * KSTR + r * KSTR + c4 * 4) * 4,
                 Kg + (size_t)(k0 + r) * (Dd / 2) + c4 * 4);
        }
        // V^T tile: 64 rows x 64 u32 = 1024 chunks -> 4 per thread
        #pragma unroll
        for (int i = 0; i < 4; i++) {
            int f = tid + i * 256;
            int r = f >> 4, c4 = f & 15;
            cp16(sV + (b * 64 * VTSTR + r * VTSTR + c4 * 4) * 4,
                 Vg + (size_t)r * (Ss / 2) + (k0 >> 1) + c4 * 4);
        }
        cp_commit();
    };

    issue_kv(0, 0);
    if (ntiles > 1) issue_kv(1, 1);

    // Stage Q tile (packed fp16x2): 128 rows x 32 u32, 16 u32 per thread
    #pragma unroll
    for (int i = 0; i < 4; i++) {
        int f = tid + i * 256;
        int r = f >> 3, c4 = f & 7;
        uint4 v = *(const uint4*)(Qg + (size_t)(q0 + r) * (Dd / 2) + c4 * 4);
        *(uint4*)(Ps + r * QSTR + c4 * 4) = v;
    }
    __syncthreads();

    // Q fragments: 4 k16 chunks over d=64
    uint32_t qf[4][4];
    #pragma unroll
    for (int kk = 0; kk < 4; kk++) {
        uint32_t addr = sP + (uint32_t)((w16 + parow) * QSTR + kk * 8 + pacol) * 4;
        ldsm_x4(qf[kk][0], qf[kk][1], qf[kk][2], qf[kk][3], addr);
    }

    float oacc[8][4];
    #pragma unroll
    for (int nf = 0; nf < 8; nf++)
        #pragma unroll
        for (int v = 0; v < 4; v++) oacc[nf][v] = 0.f;
    float mrow[2] = {-1e30f, -1e30f};
    float lrow[2] = {0.f, 0.f};

    int buf = 0;
    for (int t = 0; t < ntiles; t++) {
        if (t + 1 < ntiles) cp_wait<1>(); else cp_wait<0>();
        __syncthreads();

        const uint32_t sKb = sK + (uint32_t)(buf * 128 * KSTR) * 4;
        const uint32_t sVb = sV + (uint32_t)(buf * 64 * VTSTR) * 4;

        // S = Q @ K^T over 128 kv cols (fp16 k16: 4 kk x 8 p x 2 = 64 MMA)
        float sacc[16][4];
        #pragma unroll
        for (int nf = 0; nf < 16; nf++)
            #pragma unroll
            for (int v = 0; v < 4; v++) sacc[nf][v] = 0.f;

        #pragma unroll
        for (int kk = 0; kk < 4; kk++) {
            #pragma unroll
            for (int p = 0; p < 8; p++) {
                uint32_t addr = sKb +
                    (uint32_t)((p * 16 + kbrow) * KSTR + kk * 8 + kbcol) * 4;
                uint32_t b0a, b1a, b0b, b1b;
                ldsm_x4(b0a, b1a, b0b, b1b, addr);
                mma_f16(sacc[2 * p], qf[kk][0], qf[kk][1], qf[kk][2],
                        qf[kk][3], b0a, b1a);
                mma_f16(sacc[2 * p + 1], qf[kk][0], qf[kk][1], qf[kk][2],
                        qf[kk][3], b0b, b1b);
            }
        }

        const int kv0 = t * 128;
        const bool domask = (t == ntiles - 1);

        // Online softmax (base-2)
        #pragma unroll
        for (int r = 0; r < 2; r++) {
            const int rowg = q0 + w16 + g + 8 * r;
            float mt = -1e30f;
            #pragma unroll
            for (int nf = 0; nf < 16; nf++) {
                float s0 = sacc[nf][2 * r];
                float s1 = sacc[nf][2 * r + 1];
                if (domask) {
                    int col = kv0 + nf * 8 + 2 * tig;
                    if (col > rowg)     s0 = -1e30f;
                    if (col + 1 > rowg) s1 = -1e30f;
                }
                sacc[nf][2 * r] = s0; sacc[nf][2 * r + 1] = s1;
                mt = fmaxf(mt, fmaxf(s0, s1));
            }
            mt = fmaxf(mt, __shfl_xor_sync(0xffffffffu, mt, 1, 4));
            mt = fmaxf(mt, __shfl_xor_sync(0xffffffffu, mt, 2, 4));
            float mnew = fmaxf(mrow[r], mt);
            float corr = fast_exp2(mrow[r] - mnew);
            float rs = 0.f;
            #pragma unroll
            for (int nf = 0; nf < 16; nf++) {
                float p0 = fast_exp2(sacc[nf][2 * r] - mnew);
                float p1 = fast_exp2(sacc[nf][2 * r + 1] - mnew);
                rs += p0 + p1;
                // pack kv pair (even, odd) into one fp16x2 u32
                Ps[(w16 + g + 8 * r) * QSTR + nf * 4 + tig] = packh2(p0, p1);
            }
            rs += __shfl_xor_sync(0xffffffffu, rs, 1, 4);
            rs += __shfl_xor_sync(0xffffffffu, rs, 2, 4);
            lrow[r] = lrow[r] * corr + rs;
            mrow[r] = mnew;
            #pragma unroll
            for (int nf = 0; nf < 8; nf++) {
                oacc[nf][2 * r]     *= corr;
                oacc[nf][2 * r + 1] *= corr;
            }
        }
        __syncwarp();

        // O += P @ V over kv=128 (fp16 k16: 8 kk x 8 nf = 64 MMA)
        #pragma unroll
        for (int kk = 0; kk < 8; kk++) {
            uint32_t a0, a1, a2, a3;
            ldsm_x4(a0, a1, a2, a3,
                    sP + (uint32_t)((w16 + parow) * QSTR + kk * 8 + pacol) * 4);
            uint32_t bv_[8][2];
            #pragma unroll
            for (int p = 0; p < 4; p++) {
                uint32_t addr = sVb +
                    (uint32_t)((p * 16 + kbrow) * VTSTR + kk * 8 + kbcol) * 4;
                ldsm_x4(bv_[2 * p][0], bv_[2 * p][1],
                        bv_[2 * p + 1][0], bv_[2 * p + 1][1], addr);
            }
            #pragma unroll
            for (int nf = 0; nf < 8; nf++)
                mma_f16(oacc[nf], a0, a1, a2, a3, bv_[nf][0], bv_[nf][1]);
        }

        __syncthreads();
        if (t + 2 < ntiles) issue_kv(t + 2, buf);
        buf ^= 1;
    }

    // Epilogue: normalize + write PACKED bf16 hi/lo [B*S][kp]
    const int b = bh >> 4, h = bh & 15;
    #pragma unroll
    for (int r = 0; r < 2; r++) {
        float inv = 1.0f / lrow[r];
        int s = q0 + w16 + g + 8 * r;
        size_t rowbase = (size_t)(b * Ss + s) * KP;
        #pragma unroll
        for (int nf = 0; nf < 8; nf++) {
            int d = nf * 8 + 2 * tig;
            float o0 = oacc[nf][2 * r] * inv;
            float o1 = oacc[nf][2 * r + 1] * inv;
            uint32_t hi, lo;
            split2(o0, o1, hi, lo);
            size_t off = rowbase + ((h * Dd + d) >> 1);
            g_AOh[off] = hi;
            g_AOl[off] = lo;
        }
    }
}

// ---------------------------------------------------------------------------
// Launch
// ---------------------------------------------------------------------------
extern "C" void kernel_launch(void* const* d_in, const int* in_sizes, int n_in,
                              void* d_out, int out_size)
{
    const float* x  = (const float*)d_in[0];
    const float* Wq = (const float*)d_in[1];
    const float* bq = (const float*)d_in[2];
    const float* Wk = (const float*)d_in[3];
    const float* bk = (const float*)d_in[4];
    const float* Wv = (const float*)d_in[5];
    const float* bv = (const float*)d_in[6];
    const float* Wo = (const float*)d_in[7];
    float* out = (float*)d_out;

    static bool attr_set = false;
    if (!attr_set) {
        cudaFuncSetAttribute(proj_qkv_tc,
            cudaFuncAttributeMaxDynamicSharedMemorySize, GEMM_SMEM_BYTES);
        cudaFuncSetAttribute(out_proj_tc,
            cudaFuncAttributeMaxDynamicSharedMemorySize, GEMM_SMEM_BYTES);
        cudaFuncSetAttribute(attn_tc,
            cudaFuncAttributeMaxDynamicSharedMemorySize, ATTN_SMEM_BYTES);
        attr_set = true;
    }

    // Pre-pack weights (z 0..3) and x (z == 4)
    prep_pack<<<dim3(32, 32, 5), 256>>>(Wq, Wk, Wv, Wo, x);

    // QKV projections
    proj_qkv_tc<<<dim3(32, 8, 3), 256, GEMM_SMEM_BYTES>>>(bq, bk, bv);

    // Flash attention: 16 q-tiles x 32 (b,h)
    attn_tc<<<dim3(16, Bb * Hh), 256, ATTN_SMEM_BYTES>>>();

    // Output projection
    out_proj_tc<<<dim3(32, 8), 256, GEMM_SMEM_BYTES>>>(out);
}

// round 17
// speedup vs baseline: 1.5600x; 1.2480x over previous
#include <cuda_runtime.h>
#include <cuda_bf16.h>
#include <cuda_fp16.h>
#include <math.h>
#include <stdint.h>

// Problem constants
constexpr int Bb = 2;
constexpr int Ss = 2048;
constexpr int Ee = 1024;
constexpr int Hh = 16;
constexpr int Dd = 64;
constexpr int KP = Ee / 2;   // packed u32 (2 x 16-bit) per row

// Scratch (device globals — no allocation allowed)
// Q: pre-scaled by 0.125*log2(e), fp16x2-packed [B,H,S,D/2]. K: fp16x2 packed.
// V: fp16 TRANSPOSED [B,H,D,S].
__device__ uint32_t g_Qp[(size_t)Bb * Hh * Ss * (Dd / 2)];
__device__ uint32_t g_Kp[(size_t)Bb * Hh * Ss * (Dd / 2)];
__device__ uint32_t g_Vp[(size_t)Bb * Hh * Dd * (Ss / 2)];
// GEMM operands, fp16: weights single-precision-rounded (fp16), activations
// hi/lo fp16 split (exact to ~2^-22). u32 = 2 fp16, k-pairs minor.
__device__ uint32_t g_Wf[(size_t)4 * Ee * KP];     // weights, [z][n][kp]
__device__ uint32_t g_Xh[(size_t)Bb * Ss * KP];    // x hi, [row][kp]
__device__ uint32_t g_Xl[(size_t)Bb * Ss * KP];    // x lo
__device__ uint32_t g_AOh[(size_t)Bb * Ss * KP];   // attn out hi
__device__ uint32_t g_AOl[(size_t)Bb * Ss * KP];   // attn out lo

// ---------------------------------------------------------------------------
// Helpers
// ---------------------------------------------------------------------------
__device__ __forceinline__ float fast_exp2(float x) {
    float y;
    asm("ex2.approx.f32 %0, %1;" : "=f"(y) : "f"(x));
    return y;
}

__device__ __forceinline__ uint32_t packh2(float a, float b) {
    __half2 h = __floats2half2_rn(a, b);   // low = a, high = b
    return *(uint32_t*)&h;
}

// fp16 hi/lo split of a float pair
__device__ __forceinline__ void split2h(float v0, float v1,
                                        uint32_t& hi, uint32_t& lo) {
    float h0 = __half2float(__float2half_rn(v0));
    float h1 = __half2float(__float2half_rn(v1));
    hi = packh2(h0, h1);
    lo = packh2(v0 - h0, v1 - h1);
}

__device__ __forceinline__ void mma_f16(float c[4], uint32_t a0, uint32_t a1,
                                        uint32_t a2, uint32_t a3,
                                        uint32_t b0, uint32_t b1) {
    asm volatile(
        "mma.sync.aligned.m16n8k16.row.col.f32.f16.f16.f32 "
        "{%0,%1,%2,%3}, {%4,%5,%6,%7}, {%8,%9}, {%0,%1,%2,%3};\n"
        : "+f"(c[0]), "+f"(c[1]), "+f"(c[2]), "+f"(c[3])
        : "r"(a0), "r"(a1), "r"(a2), "r"(a3), "r"(b0), "r"(b1));
}

__device__ __forceinline__ void ldsm_x4(uint32_t& r0, uint32_t& r1,
                                        uint32_t& r2, uint32_t& r3,
                                        uint32_t saddr) {
    asm volatile(
        "ldmatrix.sync.aligned.m8n8.x4.shared.b16 {%0,%1,%2,%3}, [%4];"
        : "=r"(r0), "=r"(r1), "=r"(r2), "=r"(r3) : "r"(saddr));
}

__device__ __forceinline__ void cp16(uint32_t dst_smem, const void* src) {
    asm volatile("cp.async.cg.shared.global [%0], [%1], 16;"
                 :: "r"(dst_smem), "l"(src));
}
__device__ __forceinline__ void cp_commit() {
    asm volatile("cp.async.commit_group;");
}
template <int N>
__device__ __forceinline__ void cp_wait() {
    asm volatile("cp.async.wait_group %0;" :: "n"(N));
}

// ---------------------------------------------------------------------------
// Kernel 0: weight + x pre-pack (z<4: W transpose + fp16 round; z==4: x
// fp16 hi/lo split).
// ---------------------------------------------------------------------------
__global__ __launch_bounds__(256) void prep_pack(
    const float* __restrict__ Wq, const float* __restrict__ Wk,
    const float* __restrict__ Wv, const float* __restrict__ Wo,
    const float* __restrict__ x)
{
    __shared__ float t[32][33];
    const int z = blockIdx.z;
    const int tid = threadIdx.x;

    if (z == 4) {
        int blk = blockIdx.y * 32 + blockIdx.x;
        #pragma unroll
        for (int it = 0; it < 4; it++) {
            int idx = (blk * 4 + it) * 256 + tid;
            float4 v = ((const float4*)x)[idx];
            uint32_t h0, l0, h1, l1;
            split2h(v.x, v.y, h0, l0);
            split2h(v.z, v.w, h1, l1);
            ((uint2*)g_Xh)[idx] = make_uint2(h0, h1);
            ((uint2*)g_Xl)[idx] = make_uint2(l0, l1);
        }
        return;
    }

    const int k0 = blockIdx.x * 32, n0 = blockIdx.y * 32;
    const float* W = (z == 0) ? Wq : (z == 1) ? Wk : (z == 2) ? Wv : Wo;

    #pragma unroll
    for (int it = 0; it < 4; it++) {
        int idx = tid + it * 256;
        int kk = idx >> 5, nn = idx & 31;
        float v;
        if (z < 3) {
            int n = n0 + nn, h = n >> 6, d = n & 63;
            v = W[((size_t)h * Ee + (k0 + kk)) * Dd + d];
        } else {
            v = W[(size_t)(k0 + kk) * Ee + (n0 + nn)];
        }
        t[kk][nn] = v;
    }
    __syncthreads();

    uint32_t* wf = g_Wf + (size_t)z * Ee * KP;
    #pragma unroll
    for (int it = 0; it < 2; it++) {
        int idx = tid + it * 256;
        int nn = idx >> 4, kp = idx & 15;
        wf[(size_t)(n0 + nn) * KP + (k0 >> 1) + kp] =
            packh2(t[2 * kp][nn], t[2 * kp + 1][nn]);
    }
}

// ---------------------------------------------------------------------------
// fp16 GEMM: A = Ah + Al (fp16 split, exact), B = fp16 weights.
// acc += Ah*B + Al*B  (2 MMA passes). R11 mainloop structure: 3-stage
// cp.async ring, ONE syncthreads per k-iter, compute THEN issue, 2 CTAs/SM.
// Compact stride-16 XOR-swizzled smem. Stage: [Ah][Al][Bf] x 2048 u32.
// ---------------------------------------------------------------------------
constexpr int BM = 128, BN = 128, BK = 32;
constexpr int SEL_U32 = 128 * 16;                 // 2048 u32 per matrix sel
constexpr int STAGE_U32 = 3 * SEL_U32;            // 6144 u32 per stage
constexpr int NSTAGE = 3;
constexpr int GEMM_SMEM_BYTES = NSTAGE * STAGE_U32 * 4;   // 73728 B
constexpr int NKT = Ee / BK;                      // 32

__device__ __forceinline__ uint32_t sw_off(int row, int q) {
    return (uint32_t)(row * 16 + ((q ^ ((row >> 1) & 3)) << 2));
}

__device__ __forceinline__ void gemm_compute_f16(
    uint32_t sBase, int st, int wm, int wn, int lane, float acc[4][4][4])
{
    const uint32_t aHi = sBase + (st * STAGE_U32) * 4;
    const uint32_t aLo = aHi + SEL_U32 * 4;
    const uint32_t bF  = aHi + 2 * SEL_U32 * 4;
    const int mIdx = lane >> 3, lr = lane & 7;
    const int arow = (mIdx & 1) * 8 + lr, acol = (mIdx >> 1) * 4;
    const int brow = (mIdx >> 1) * 8 + lr, bcol = (mIdx & 1) * 4;

    #pragma unroll
    for (int s = 0; s < 2; s++) {
        const int cb = 8 * s;
        uint32_t bf_[4][2];
        #pragma unroll
        for (int p = 0; p < 2; p++) {
            int rowB = wn * 32 + p * 16 + brow;
            uint32_t off = sw_off(rowB, (cb + bcol) >> 2) * 4;
            ldsm_x4(bf_[2 * p][0], bf_[2 * p][1],
                    bf_[2 * p + 1][0], bf_[2 * p + 1][1], bF + off);
        }
        #pragma unroll
        for (int mt = 0; mt < 4; mt++) {
            int rowA = wm * 64 + mt * 16 + arow;
            uint32_t off = sw_off(rowA, (cb + acol) >> 2) * 4;
            uint32_t ah0, ah1, ah2, ah3, al0, al1, al2, al3;
            ldsm_x4(ah0, ah1, ah2, ah3, aHi + off);
            ldsm_x4(al0, al1, al2, al3, aLo + off);
            #pragma unroll
            for (int nt = 0; nt < 4; nt++)
                mma_f16(acc[mt][nt], ah0, ah1, ah2, ah3, bf_[nt][0], bf_[nt][1]);
            #pragma unroll
            for (int nt = 0; nt < 4; nt++)
                mma_f16(acc[mt][nt], al0, al1, al2, al3, bf_[nt][0], bf_[nt][1]);
        }
    }
}

__device__ __forceinline__ void gemm_issue(
    uint32_t sBase, int st, int kt, int tid, int m0, int n0,
    const uint32_t* gAh, const uint32_t* gAl, const uint32_t* gBf)
{
    const uint32_t stBase = sBase + (st * STAGE_U32) * 4;
    #pragma unroll
    for (int i = 0; i < 2; i++) {
        int f = tid + i * 256;
        int row = f >> 2, c4 = f & 3;
        uint32_t off = sw_off(row, c4) * 4;
        size_t oa = (size_t)(m0 + row) * KP + kt * 16 + c4 * 4;
        cp16(stBase + off, gAh + oa);
        cp16(stBase + SEL_U32 * 4 + off, gAl + oa);
        size_t ob = (size_t)(n0 + row) * KP + kt * 16 + c4 * 4;
        cp16(stBase + 2 * SEL_U32 * 4 + off, gBf + ob);
    }
    cp_commit();
}

__device__ __forceinline__ void gemm_mainloop(
    uint32_t sBase, int tid, int wm, int wn, int lane, int m0, int n0,
    const uint32_t* gAh, const uint32_t* gAl, const uint32_t* gBf,
    float acc[4][4][4])
{
    gemm_issue(sBase, 0, 0, tid, m0, n0, gAh, gAl, gBf);
    gemm_issue(sBase, 1, 1, tid, m0, n0, gAh, gAl, gBf);

    int st = 0;
    for (int kt = 0; kt < NKT; kt++) {
        if (kt + 1 < NKT) cp_wait<1>(); else cp_wait<0>();
        __syncthreads();
        gemm_compute_f16(sBase, st, wm, wn, lane, acc);
        if (kt + 2 < NKT) {
            int st2 = st + 2; if (st2 >= NSTAGE) st2 -= NSTAGE;
            gemm_issue(sBase, st2, kt + 2, tid, m0, n0, gAh, gAl, gBf);
        }
        if (++st == NSTAGE) st = 0;
    }
}

// ---------------------------------------------------------------------------
// Kernel 1: fused QKV projection. Outputs fp16: Q (pre-scaled) / K packed
// half2 [B,H,S,D/2]; V fp16 transposed [B,H,D,S].
// ---------------------------------------------------------------------------
__global__ __launch_bounds__(256, 2) void proj_qkv_tc(
    const float* __restrict__ bq, const float* __restrict__ bk,
    const float* __restrict__ bv)
{
    extern __shared__ uint32_t sm[];
    const int tid = threadIdx.x;
    const int lane = tid & 31, wid = tid >> 5;
    const int wm = wid >> 2, wn = wid & 3;
    const int g = lane >> 2, tig = lane & 3;

    const int z = blockIdx.z;
    const float* bias = (z == 0) ? bq : (z == 1) ? bk : bv;
    const float oscale = (z == 0) ? 0.125f * 1.44269504089f : 1.0f;
    const uint32_t* gBf = g_Wf + (size_t)z * Ee * KP;

    const int m0 = blockIdx.x * BM;
    const int n0 = blockIdx.y * BN;

    uint32_t sBase = (uint32_t)__cvta_generic_to_shared(sm);

    float acc[4][4][4];
    #pragma unroll
    for (int mt = 0; mt < 4; mt++)
        #pragma unroll
        for (int nt = 0; nt < 4; nt++)
            #pragma unroll
            for (int v = 0; v < 4; v++) acc[mt][nt][v] = 0.f;

    gemm_mainloop(sBase, tid, wm, wn, lane, m0, n0, g_Xh, g_Xl, gBf, acc);

    #pragma unroll
    for (int mt = 0; mt < 4; mt++) {
        #pragma unroll
        for (int nt = 0; nt < 4; nt++) {
            int col = n0 + wn * 32 + nt * 8 + tig * 2;
            int h = col >> 6, d = col & 63;
            float b0 = bias[h * Dd + d], b1 = bias[h * Dd + d + 1];
            int m = m0 + wm * 64 + mt * 16 + g;
            #pragma unroll
            for (int rr = 0; rr < 2; rr++) {
                int row = m + rr * 8;
                int b = row >> 11, s = row & 2047;
                float v0 = (acc[mt][nt][rr * 2 + 0] + b0) * oscale;
                float v1 = (acc[mt][nt][rr * 2 + 1] + b1) * oscale;
                if (z == 2) {
                    __half* vt = (__half*)g_Vp;
                    size_t base = ((size_t)(b * Hh + h) * Dd + d) * Ss + s;
                    vt[base]      = __float2half_rn(v0);
                    vt[base + Ss] = __float2half_rn(v1);
                } else {
                    uint32_t* out = (z == 0) ? g_Qp : g_Kp;
                    out[((size_t)(b * Hh + h) * Ss + s) * (Dd / 2) + (d >> 1)] =
                        packh2(v0, v1);
                }
            }
        }
    }
}

// ---------------------------------------------------------------------------
// Kernel 3: output projection (reads packed attn output).
// ---------------------------------------------------------------------------
__global__ __launch_bounds__(256, 2) void out_proj_tc(float* __restrict__ out)
{
    extern __shared__ uint32_t sm[];
    const int tid = threadIdx.x;
    const int lane = tid & 31, wid = tid >> 5;
    const int wm = wid >> 2, wn = wid & 3;
    const int g = lane >> 2, tig = lane & 3;

    const uint32_t* gBf = g_Wf + (size_t)3 * Ee * KP;

    const int m0 = blockIdx.x * BM;
    const int n0 = blockIdx.y * BN;

    uint32_t sBase = (uint32_t)__cvta_generic_to_shared(sm);

    float acc[4][4][4];
    #pragma unroll
    for (int mt = 0; mt < 4; mt++)
        #pragma unroll
        for (int nt = 0; nt < 4; nt++)
            #pragma unroll
            for (int v = 0; v < 4; v++) acc[mt][nt][v] = 0.f;

    gemm_mainloop(sBase, tid, wm, wn, lane, m0, n0, g_AOh, g_AOl, gBf, acc);

    #pragma unroll
    for (int mt = 0; mt < 4; mt++) {
        #pragma unroll
        for (int nt = 0; nt < 4; nt++) {
            int col = n0 + wn * 32 + nt * 8 + tig * 2;
            int m = m0 + wm * 64 + mt * 16 + g;
            #pragma unroll
            for (int rr = 0; rr < 2; rr++) {
                int row = m + rr * 8;
                out[(size_t)row * Ee + col]     = acc[mt][nt][rr * 2 + 0];
                out[(size_t)row * Ee + col + 1] = acc[mt][nt][rr * 2 + 1];
            }
        }
    }
}

// ---------------------------------------------------------------------------
// Kernel 2: causal flash attention, fp16 m16n8k16 MMA (exact R16).
// q/KV tiles 128, 256 threads, double-buffered cp.async, base-2 softmax.
// Epilogue writes AO as fp16 hi/lo packed.
// ---------------------------------------------------------------------------
constexpr int QSTR = 68;
constexpr int KSTR = 36;
constexpr int VTSTR = 68;
constexpr int ATTN_SMEM_BYTES =
    (128 * QSTR + 2 * 128 * KSTR + 2 * 64 * VTSTR) * 4;  // 106496 B

__global__ __launch_bounds__(256, 1) void attn_tc()
{
    extern __shared__ uint32_t smu[];
    uint32_t* Ps = smu;                        // [128][68]  Q then P
    uint32_t* Ks = smu + 128 * QSTR;           // [2][128][36]
    uint32_t* Vs = Ks + 2 * 128 * KSTR;        // [2][64][68]

    const int qt = 15 - (int)blockIdx.x;
    const int bh = blockIdx.y;
    const int q0 = qt * 128;
    const int ntiles = qt + 1;

    const uint32_t* Qg = g_Qp + (size_t)bh * Ss * (Dd / 2);
    const uint32_t* Kg = g_Kp + (size_t)bh * Ss * (Dd / 2);
    const uint32_t* Vg = g_Vp + (size_t)bh * Dd * (Ss / 2);

    const int tid = threadIdx.x;
    const int lane = tid & 31;
    const int w = tid >> 5;
    const int g = lane >> 2;
    const int tig = lane & 3;
    const int w16 = w * 16;
    const int mIdx = lane >> 3, lr = lane & 7;
    const int parow = (mIdx & 1) * 8 + lr, pacol = (mIdx >> 1) * 4;
    const int kbrow = (mIdx >> 1) * 8 + lr, kbcol = (mIdx & 1) * 4;

    const uint32_t sP = (uint32_t)__cvta_generic_to_shared(Ps);
    const uint32_t sK = (uint32_t)__cvta_generic_to_shared(Ks);
    const uint32_t sV = (uint32_t)__cvta_generic_to_shared(Vs);

    auto issue_kv = [&](int t, int b) {
        const int k0 = t * 128;
        #pragma unroll
        for (int i = 0; i < 4; i++) {
            int f = tid + i * 256;
            int r = f >> 3, c4 = f & 7;
            cp16(sK + (b * 128 * KSTR + r * KSTR + c4 * 4) * 4,
                 Kg + (size_t)(k0 + r) * (Dd / 2) + c4 * 4);
        }
        #pragma unroll
        for (int i = 0; i < 4; i++) {
            int f = tid + i * 256;
            int r = f >> 4, c4 = f & 15;
            cp16(sV + (b * 64 * VTSTR + r * VTSTR + c4 * 4) * 4,
                 Vg + (size_t)r * (Ss / 2) + (k0 >> 1) + c4 * 4);
        }
        cp_commit();
    };

    issue_kv(0, 0);
    if (ntiles > 1) issue_kv(1, 1);

    #pragma unroll
    for (int i = 0; i < 4; i++) {
        int f = tid + i * 256;
        int r = f >> 3, c4 = f & 7;
        uint4 v = *(const uint4*)(Qg + (size_t)(q0 + r) * (Dd / 2) + c4 * 4);
        *(uint4*)(Ps + r * QSTR + c4 * 4) = v;
    }
    __syncthreads();

    uint32_t qf[4][4];
    #pragma unroll
    for (int kk = 0; kk < 4; kk++) {
        uint32_t addr = sP + (uint32_t)((w16 + parow) * QSTR + kk * 8 + pacol) * 4;
        ldsm_x4(qf[kk][0], qf[kk][1], qf[kk][2], qf[kk][3], addr);
    }

    float oacc[8][4];
    #pragma unroll
    for (int nf = 0; nf < 8; nf++)
        #pragma unroll
        for (int v = 0; v < 4; v++) oacc[nf][v] = 0.f;
    float mrow[2] = {-1e30f, -1e30f};
    float lrow[2] = {0.f, 0.f};

    int buf = 0;
    for (int t = 0; t < ntiles; t++) {
        if (t + 1 < ntiles) cp_wait<1>(); else cp_wait<0>();
        __syncthreads();

        const uint32_t sKb = sK + (uint32_t)(buf * 128 * KSTR) * 4;
        const uint32_t sVb = sV + (uint32_t)(buf * 64 * VTSTR) * 4;

        float sacc[16][4];
        #pragma unroll
        for (int nf = 0; nf < 16; nf++)
            #pragma unroll
            for (int v = 0; v < 4; v++) sacc[nf][v] = 0.f;

        #pragma unroll
        for (int kk = 0; kk < 4; kk++) {
            #pragma unroll
            for (int p = 0; p < 8; p++) {
                uint32_t addr = sKb +
                    (uint32_t)((p * 16 + kbrow) * KSTR + kk * 8 + kbcol) * 4;
                uint32_t b0a, b1a, b0b, b1b;
                ldsm_x4(b0a, b1a, b0b, b1b, addr);
                mma_f16(sacc[2 * p], qf[kk][0], qf[kk][1], qf[kk][2],
                        qf[kk][3], b0a, b1a);
                mma_f16(sacc[2 * p + 1], qf[kk][0], qf[kk][1], qf[kk][2],
                        qf[kk][3], b0b, b1b);
            }
        }

        const int kv0 = t * 128;
        const bool domask = (t == ntiles - 1);

        #pragma unroll
        for (int r = 0; r < 2; r++) {
            const int rowg = q0 + w16 + g + 8 * r;
            float mt = -1e30f;
            #pragma unroll
            for (int nf = 0; nf < 16; nf++) {
                float s0 = sacc[nf][2 * r];
                float s1 = sacc[nf][2 * r + 1];
                if (domask) {
                    int col = kv0 + nf * 8 + 2 * tig;
                    if (col > rowg)     s0 = -1e30f;
                    if (col + 1 > rowg) s1 = -1e30f;
                }
                sacc[nf][2 * r] = s0; sacc[nf][2 * r + 1] = s1;
                mt = fmaxf(mt, fmaxf(s0, s1));
            }
            mt = fmaxf(mt, __shfl_xor_sync(0xffffffffu, mt, 1, 4));
            mt = fmaxf(mt, __shfl_xor_sync(0xffffffffu, mt, 2, 4));
            float mnew = fmaxf(mrow[r], mt);
            float corr = fast_exp2(mrow[r] - mnew);
            float rs = 0.f;
            #pragma unroll
            for (int nf = 0; nf < 16; nf++) {
                float p0 = fast_exp2(sacc[nf][2 * r] - mnew);
                float p1 = fast_exp2(sacc[nf][2 * r + 1] - mnew);
                rs += p0 + p1;
                Ps[(w16 + g + 8 * r) * QSTR + nf * 4 + tig] = packh2(p0, p1);
            }
            rs += __shfl_xor_sync(0xffffffffu, rs, 1, 4);
            rs += __shfl_xor_sync(0xffffffffu, rs, 2, 4);
            lrow[r] = lrow[r] * corr + rs;
            mrow[r] = mnew;
            #pragma unroll
            for (int nf = 0; nf < 8; nf++) {
                oacc[nf][2 * r]     *= corr;
                oacc[nf][2 * r + 1] *= corr;
            }
        }
        __syncwarp();

        #pragma unroll
        for (int kk = 0; kk < 8; kk++) {
            uint32_t a0, a1, a2, a3;
            ldsm_x4(a0, a1, a2, a3,
                    sP + (uint32_t)((w16 + parow) * QSTR + kk * 8 + pacol) * 4);
            uint32_t bv_[8][2];
            #pragma unroll
            for (int p = 0; p < 4; p++) {
                uint32_t addr = sVb +
                    (uint32_t)((p * 16 + kbrow) * VTSTR + kk * 8 + kbcol) * 4;
                ldsm_x4(bv_[2 * p][0], bv_[2 * p][1],
                        bv_[2 * p + 1][0], bv_[2 * p + 1][1], addr);
            }
            #pragma unroll
            for (int nf = 0; nf < 8; nf++)
                mma_f16(oacc[nf], a0, a1, a2, a3, bv_[nf][0], bv_[nf][1]);
        }

        __syncthreads();
        if (t + 2 < ntiles) issue_kv(t + 2, buf);
        buf ^= 1;
    }

    // Epilogue: normalize + write PACKED fp16 hi/lo [B*S][kp]
    const int b = bh >> 4, h = bh & 15;
    #pragma unroll
    for (int r = 0; r < 2; r++) {
        float inv = 1.0f / lrow[r];
        int s = q0 + w16 + g + 8 * r;
        size_t rowbase = (size_t)(b * Ss + s) * KP;
        #pragma unroll
        for (int nf = 0; nf < 8; nf++) {
            int d = nf * 8 + 2 * tig;
            float o0 = oacc[nf][2 * r] * inv;
            float o1 = oacc[nf][2 * r + 1] * inv;
            uint32_t hi, lo;
            split2h(o0, o1, hi, lo);
            size_t off = rowbase + ((h * Dd + d) >> 1);
            g_AOh[off] = hi;
            g_AOl[off] = lo;
        }
    }
}

// ---------------------------------------------------------------------------
// Launch
// ---------------------------------------------------------------------------
extern "C" void kernel_launch(void* const* d_in, const int* in_sizes, int n_in,
                              void* d_out, int out_size)
{
    const float* x  = (const float*)d_in[0];
    const float* Wq = (const float*)d_in[1];
    const float* bq = (const float*)d_in[2];
    const float* Wk = (const float*)d_in[3];
    const float* bk = (const float*)d_in[4];
    const float* Wv = (const float*)d_in[5];
    const float* bv = (const float*)d_in[6];
    const float* Wo = (const float*)d_in[7];
    float* out = (float*)d_out;

    static bool attr_set = false;
    if (!attr_set) {
        cudaFuncSetAttribute(proj_qkv_tc,
            cudaFuncAttributeMaxDynamicSharedMemorySize, GEMM_SMEM_BYTES);
        cudaFuncSetAttribute(out_proj_tc,
            cudaFuncAttributeMaxDynamicSharedMemorySize, GEMM_SMEM_BYTES);
        cudaFuncSetAttribute(attn_tc,
            cudaFuncAttributeMaxDynamicSharedMemorySize, ATTN_SMEM_BYTES);
        attr_set = true;
    }

    // Pre-pack weights (z 0..3, fp16) and x (z == 4, fp16 hi/lo)
    prep_pack<<<dim3(32, 32, 5), 256>>>(Wq, Wk, Wv, Wo, x);

    // QKV projections
    proj_qkv_tc<<<dim3(32, 8, 3), 256, GEMM_SMEM_BYTES>>>(bq, bk, bv);

    // Flash attention: 16 q-tiles x 32 (b,h)
    attn_tc<<<dim3(16, Bb * Hh), 256, ATTN_SMEM_BYTES>>>();

    // Output projection
    out_proj_tc<<<dim3(32, 8), 256, GEMM_SMEM_BYTES>>>(out);
}